// round 1
// baseline (speedup 1.0000x reference)
#include <cuda_runtime.h>
#include <math.h>

#define NN 8192
#define EE 131072
#define HH 256

// ---------------- scratch (device globals; no allocations allowed) ----------------
__device__ __align__(16) float g_feat[EE * 40];
__device__ __align__(16) float g_u[EE];
__device__ __align__(16) float g_Y[EE * 16];
__device__ __align__(16) float g_x[EE * HH];
__device__ __align__(16) float g_t[EE * HH];
__device__ __align__(16) float g_s16[EE * 16];   // xv, then per-layer w
__device__ __align__(16) float g_V[EE * 256];
__device__ __align__(16) float g_VV0[EE * 16];
__device__ __align__(16) float g_wY[NN * 256];

// ---------------- geometry: d, envelope, bessel, gathered attrs, sph harm ----------
__global__ void k_geom(const float* __restrict__ vec, const float* __restrict__ attrs,
                       const int* __restrict__ snd, const int* __restrict__ rcv,
                       float* __restrict__ feat, float* __restrict__ uo, float* __restrict__ Yo)
{
    int e = blockIdx.x * blockDim.x + threadIdx.x;
    if (e >= EE) return;
    float vx = vec[3*e+0], vy = vec[3*e+1], vz = vec[3*e+2];
    float d2 = vx*vx + vy*vy + vz*vz;
    float d  = sqrtf(d2);
    float d6 = d2 * d2 * d2;
    // p=6: u = 1 - 28 d^6 + 48 d^7 - 21 d^8   (d < 1 always here)
    float env = 1.0f + d6 * (-28.0f + d * (48.0f - 21.0f * d));
    uo[e] = env;
    float invd = 1.0f / d;
    const float S2 = 1.4142135623730951f; // sqrt(2/CUTOFF)
    float* fp = feat + (size_t)e * 40;
    #pragma unroll
    for (int k = 1; k <= 8; k++)
        fp[k-1] = S2 * sinpif((float)k * d) * invd;   // sin(k*pi*d)/d, accurate
    int s = snd[e], r = rcv[e];
    #pragma unroll
    for (int i = 0; i < 16; i++) fp[8 + i]  = attrs[s*16 + i];
    #pragma unroll
    for (int i = 0; i < 16; i++) fp[24 + i] = attrs[r*16 + i];

    float x = vx*invd, y = vy*invd, z = vz*invd;
    const float s3  = 1.7320508075688772f;
    const float s5  = 2.2360679774997896f;
    const float s15 = 3.8729833462074170f;
    const float s7  = 2.6457513110645907f;
    const float c33 = 2.0916500663351885f;  // sqrt(35/8)
    const float c32 = 10.246950765959598f;  // sqrt(105)
    const float c31 = 1.6201851746019649f;  // sqrt(21/8)
    float* Yp = Yo + (size_t)e * 16;
    Yp[0]  = 1.0f;
    Yp[1]  = s3 * x;
    Yp[2]  = s3 * y;
    Yp[3]  = s3 * z;
    Yp[4]  = s15 * x * y;
    Yp[5]  = s15 * y * z;
    Yp[6]  = 0.5f * s5 * (3.0f*z*z - 1.0f);
    Yp[7]  = s15 * x * z;
    Yp[8]  = 0.5f * s15 * (x*x - y*y);
    Yp[9]  = c33 * y * (3.0f*x*x - y*y);
    Yp[10] = c32 * x * y * z;
    Yp[11] = c31 * y * (5.0f*z*z - 1.0f);
    Yp[12] = 0.5f * s7 * (5.0f*z*z*z - 3.0f*z);
    Yp[13] = c31 * x * (5.0f*z*z - 1.0f);
    Yp[14] = 0.5f * c32 * z * (x*x - y*y);
    Yp[15] = c33 * x * (x*x - 3.0f*y*y);
}

// ---------------- fp32 SGEMM 128x128x16, fused epilogues ----------------
// EPI: 0 = none, 1 = silu, 2 = u*silu, 3 = C = (C + u*silu)/sqrt(2)
__device__ __forceinline__ float silu_f(float t) { return t / (1.0f + __expf(-t)); }

template<int EPI>
__global__ __launch_bounds__(256)
void sgemm(const float* __restrict__ A1, int K1, const float* __restrict__ A2,
           const float* __restrict__ B, const float* __restrict__ bias,
           const float* __restrict__ u, float* __restrict__ C,
           int K, int Ncols)
{
    __shared__ __align__(16) float As[16][132];
    __shared__ __align__(16) float Bs[16][132];
    int tid = threadIdx.x;
    int tx = tid & 15, ty = tid >> 4;
    int rowBase = blockIdx.y * 128;
    int colBase = blockIdx.x * 128;
    float acc[2][2][4][4];
    #pragma unroll
    for (int a = 0; a < 2; a++)
        #pragma unroll
        for (int b = 0; b < 2; b++)
            #pragma unroll
            for (int i = 0; i < 4; i++)
                #pragma unroll
                for (int j = 0; j < 4; j++) acc[a][b][i][j] = 0.f;

    int ktiles = (K + 15) >> 4;
    for (int kt = 0; kt < ktiles; kt++) {
        // A tile: 128 rows x 16 k
        #pragma unroll
        for (int s = 0; s < 2; s++) {
            int f = tid + s * 256;           // 0..511 float4 slots
            int row = f >> 2, kq = f & 3;
            int k0 = kt * 16 + kq * 4;
            int grow = rowBase + row;
            float4 v;
            if (k0 + 3 < K1) {
                v = *(const float4*)(A1 + (size_t)grow * K1 + k0);
            } else if (A2 != nullptr && k0 >= K1 && k0 + 3 < K) {
                v = *(const float4*)(A2 + (size_t)grow * 16 + (k0 - K1));
            } else {
                float t0 = (k0+0 < K) ? ((k0+0 < K1) ? A1[(size_t)grow*K1 + k0+0] : A2[(size_t)grow*16 + k0+0-K1]) : 0.f;
                float t1 = (k0+1 < K) ? ((k0+1 < K1) ? A1[(size_t)grow*K1 + k0+1] : A2[(size_t)grow*16 + k0+1-K1]) : 0.f;
                float t2 = (k0+2 < K) ? ((k0+2 < K1) ? A1[(size_t)grow*K1 + k0+2] : A2[(size_t)grow*16 + k0+2-K1]) : 0.f;
                float t3 = (k0+3 < K) ? ((k0+3 < K1) ? A1[(size_t)grow*K1 + k0+3] : A2[(size_t)grow*16 + k0+3-K1]) : 0.f;
                v = make_float4(t0, t1, t2, t3);
            }
            As[kq*4+0][row] = v.x; As[kq*4+1][row] = v.y;
            As[kq*4+2][row] = v.z; As[kq*4+3][row] = v.w;
        }
        // B tile: 16 k x 128 cols
        #pragma unroll
        for (int s = 0; s < 2; s++) {
            int f = tid + s * 256;
            int krow = f >> 5, colq = f & 31;
            int gk = kt * 16 + krow;
            float4 bv = make_float4(0.f, 0.f, 0.f, 0.f);
            if (gk < K) bv = *(const float4*)(B + (size_t)gk * Ncols + colBase + colq * 4);
            *(float4*)&Bs[krow][colq * 4] = bv;
        }
        __syncthreads();
        #pragma unroll
        for (int kk = 0; kk < 16; kk++) {
            float4 av[2], bv[2];
            av[0] = *(const float4*)&As[kk][ty * 4];
            av[1] = *(const float4*)&As[kk][64 + ty * 4];
            bv[0] = *(const float4*)&Bs[kk][tx * 4];
            bv[1] = *(const float4*)&Bs[kk][64 + tx * 4];
            const float* a = (const float*)av;
            const float* b = (const float*)bv;
            #pragma unroll
            for (int ri = 0; ri < 2; ri++)
                #pragma unroll
                for (int ci = 0; ci < 2; ci++)
                    #pragma unroll
                    for (int i = 0; i < 4; i++)
                        #pragma unroll
                        for (int j = 0; j < 4; j++)
                            acc[ri][ci][i][j] += a[ri*4+i] * b[ci*4+j];
        }
        __syncthreads();
    }

    #pragma unroll
    for (int ri = 0; ri < 2; ri++)
        #pragma unroll
        for (int i = 0; i < 4; i++) {
            int row = rowBase + ri * 64 + ty * 4 + i;
            float uv = (EPI == 2 || EPI == 3) ? u[row] : 0.f;
            #pragma unroll
            for (int ci = 0; ci < 2; ci++) {
                int col = colBase + ci * 64 + tx * 4;
                float o[4];
                #pragma unroll
                for (int j = 0; j < 4; j++) {
                    float t = acc[ri][ci][i][j] + bias[col + j];
                    if (EPI == 0) { o[j] = t; }
                    else {
                        float sv = silu_f(t);
                        if (EPI == 1) o[j] = sv;
                        else o[j] = uv * sv;   // EPI 2 and partial EPI 3
                    }
                }
                float* cp = C + (size_t)row * Ncols + col;
                if (EPI == 3) {
                    float4 old = *(const float4*)cp;
                    const float RS2 = 0.7071067811865476f;
                    o[0] = (old.x + o[0]) * RS2;
                    o[1] = (old.y + o[1]) * RS2;
                    o[2] = (old.z + o[2]) * RS2;
                    o[3] = (old.w + o[3]) * RS2;
                }
                *(float4*)cp = make_float4(o[0], o[1], o[2], o[3]);
            }
        }
}

// ---------------- (E,256) @ (256,16) GEMM ----------------
__global__ __launch_bounds__(128)
void gemm_n16(const float* __restrict__ X, const float* __restrict__ W, float* __restrict__ S)
{
    __shared__ __align__(16) float Ws[4096];
    __shared__ __align__(16) float Xs[8][256];
    int tid = threadIdx.x;
    size_t e0 = (size_t)blockIdx.x * 8;
    #pragma unroll
    for (int s = 0; s < 8; s++)
        ((float4*)Ws)[tid + s * 128] = ((const float4*)W)[tid + s * 128];
    #pragma unroll
    for (int s = 0; s < 4; s++) {
        int f = tid + s * 128;
        int row = f >> 6, q = f & 63;
        ((float4*)Xs[row])[q] = *(const float4*)(X + (e0 + row) * 256 + q * 4);
    }
    __syncthreads();
    int e = tid >> 4, c = tid & 15;
    float acc = 0.f;
    const float* xr = Xs[e];
    #pragma unroll 16
    for (int k = 0; k < 256; k++)
        acc += xr[k] * Ws[k * 16 + c];
    S[(e0 + e) * 16 + c] = acc;
}

// ---------------- V[e,m,:] = xv[e,m] * Y[e,:] ----------------
__global__ void k_buildV(const float* __restrict__ xv, const float* __restrict__ Y, float* __restrict__ V)
{
    int idx = blockIdx.x * blockDim.x + threadIdx.x;   // e*16 + m
    float w = xv[idx];
    int e = idx >> 4;
    const float4* Y4 = (const float4*)(Y + (size_t)e * 16);
    float4* V4 = (float4*)(V + (size_t)idx * 16);
    #pragma unroll
    for (int q = 0; q < 4; q++) {
        float4 y = Y4[q];
        V4[q] = make_float4(w*y.x, w*y.y, w*y.z, w*y.w);
    }
}

// ---------------- zero ----------------
__global__ void k_zero4(float4* p, int n4)
{
    int i = blockIdx.x * blockDim.x + threadIdx.x;
    if (i < n4) p[i] = make_float4(0.f, 0.f, 0.f, 0.f);
}

// ---------------- segment_sum scatter: wY[snd[e]] += w[e,m]*Y[e,i] ----------------
__global__ void k_scatter(const float* __restrict__ w, const float* __restrict__ Y,
                          const int* __restrict__ snd, float* __restrict__ wY)
{
    int idx = blockIdx.x * blockDim.x + threadIdx.x;   // e*16 + m
    int e = idx >> 4, m = idx & 15;
    float wv = w[idx];
    int s = snd[e];
    float* base = wY + (size_t)s * 256 + m * 16;
    const float4* Y4 = (const float4*)(Y + (size_t)e * 16);
    #pragma unroll
    for (int q = 0; q < 4; q++) {
        float4 y = Y4[q];
        atomicAdd(base + q*4 + 0, wv * y.x);
        atomicAdd(base + q*4 + 1, wv * y.y);
        atomicAdd(base + q*4 + 2, wv * y.z);
        atomicAdd(base + q*4 + 3, wv * y.w);
    }
}

// ---------------- per-(e,m): VV = inv*wY[snd]*V; V = VV @ W_lsh; VV0 out ----------------
__global__ __launch_bounds__(256)
void k_update(const int* __restrict__ snd, const float* __restrict__ wY,
              float* __restrict__ V, float* __restrict__ VV0, const float* __restrict__ Wlsh)
{
    __shared__ float Wsh[256];
    int tid = threadIdx.x;
    Wsh[tid] = Wlsh[tid];
    __syncthreads();
    int idx = blockIdx.x * 256 + tid;   // e*16 + m
    int e = idx >> 4, m = idx & 15;
    int s = snd[e];
    const float4* wyp = (const float4*)(wY + (size_t)s * 256 + m * 16);
    float4* vp = (float4*)(V + (size_t)idx * 16);
    float vv[16];
    #pragma unroll
    for (int q = 0; q < 4; q++) {
        float4 a = wyp[q];
        float4 b = vp[q];
        vv[q*4+0] = 0.25f * a.x * b.x;
        vv[q*4+1] = 0.25f * a.y * b.y;
        vv[q*4+2] = 0.25f * a.z * b.z;
        vv[q*4+3] = 0.25f * a.w * b.w;
    }
    VV0[idx] = vv[0];
    float o[16];
    #pragma unroll
    for (int j = 0; j < 16; j++) o[j] = 0.f;
    #pragma unroll
    for (int i = 0; i < 16; i++) {
        float t = vv[i];
        #pragma unroll
        for (int j = 0; j < 16; j++) o[j] += t * Wsh[i * 16 + j];
    }
    #pragma unroll
    for (int q = 0; q < 4; q++)
        vp[q] = make_float4(o[q*4], o[q*4+1], o[q*4+2], o[q*4+3]);
}

// ---------------- final: out[rcv[e]] += inv * u[e] * dot(x[e], W_out) ----------------
__global__ __launch_bounds__(256)
void k_final(const float* __restrict__ x, const float* __restrict__ u,
             const int* __restrict__ rcv, const float* __restrict__ Wout,
             float* __restrict__ out)
{
    __shared__ float Wo[256];
    int tid = threadIdx.x;
    Wo[tid] = Wout[tid];
    __syncthreads();
    int warp = tid >> 5, lane = tid & 31;
    size_t e = (size_t)blockIdx.x * 8 + warp;
    float p = 0.f;
    #pragma unroll
    for (int k = lane; k < 256; k += 32)
        p += x[e * 256 + k] * Wo[k];
    #pragma unroll
    for (int off = 16; off; off >>= 1)
        p += __shfl_xor_sync(0xffffffffu, p, off);
    if (lane == 0)
        atomicAdd(&out[rcv[e]], p * u[e] * 0.25f);
}

// ---------------- host ----------------
extern "C" void kernel_launch(void* const* d_in, const int* in_sizes, int n_in,
                              void* d_out, int out_size)
{
    const float* attrs = (const float*)d_in[0];
    const float* vec   = (const float*)d_in[1];
    const int*   snd   = (const int*)d_in[2];
    const int*   rcv   = (const int*)d_in[3];
    const float* We0   = (const float*)d_in[4];
    const float* be0   = (const float*)d_in[5];
    const float* We1   = (const float*)d_in[6];
    const float* be1   = (const float*)d_in[7];
    const float* Wv0   = (const float*)d_in[8];
    const float* Wlw   = (const float*)d_in[9];
    const float* Wlsh  = (const float*)d_in[10];
    const float* Wly1  = (const float*)d_in[11];
    const float* bly1  = (const float*)d_in[12];
    const float* Wly2  = (const float*)d_in[13];
    const float* bly2  = (const float*)d_in[14];
    const float* Wout  = (const float*)d_in[15];
    float* out = (float*)d_out;

    float *feat, *uu, *Y, *x, *t, *s16, *V, *VV0, *wY;
    cudaGetSymbolAddress((void**)&feat, g_feat);
    cudaGetSymbolAddress((void**)&uu,   g_u);
    cudaGetSymbolAddress((void**)&Y,    g_Y);
    cudaGetSymbolAddress((void**)&x,    g_x);
    cudaGetSymbolAddress((void**)&t,    g_t);
    cudaGetSymbolAddress((void**)&s16,  g_s16);
    cudaGetSymbolAddress((void**)&V,    g_V);
    cudaGetSymbolAddress((void**)&VV0,  g_VV0);
    cudaGetSymbolAddress((void**)&wY,   g_wY);

    dim3 gg(2, 1024);     // 256 cols / 128, 131072 rows / 128

    k_geom<<<EE / 256, 256>>>(vec, attrs, snd, rcv, feat, uu, Y);
    sgemm<1><<<gg, 256>>>(feat, 40, nullptr, We0, be0, nullptr, t, 40, 256);
    sgemm<2><<<gg, 256>>>(t, 256, nullptr, We1, be1, uu, x, 256, 256);
    gemm_n16<<<EE / 8, 128>>>(x, Wv0, s16);
    k_buildV<<<EE * 16 / 256, 256>>>(s16, Y, V);

    for (int l = 0; l < 2; l++) {
        gemm_n16<<<EE / 8, 128>>>(x, Wlw + (size_t)l * 256 * 16, s16);
        k_zero4<<<(NN * 256 / 4 + 255) / 256, 256>>>((float4*)wY, NN * 256 / 4);
        k_scatter<<<EE * 16 / 256, 256>>>(s16, Y, snd, wY);
        k_update<<<EE * 16 / 256, 256>>>(snd, wY, V, VV0, Wlsh + (size_t)l * 256);
        sgemm<1><<<gg, 256>>>(x, 256, VV0, Wly1 + (size_t)l * 272 * 256,
                              bly1 + (size_t)l * 256, nullptr, t, 272, 256);
        sgemm<3><<<gg, 256>>>(t, 256, nullptr, Wly2 + (size_t)l * 256 * 256,
                              bly2 + (size_t)l * 256, uu, x, 256, 256);
    }

    k_zero4<<<(NN / 4 + 255) / 256, 256>>>((float4*)out, NN / 4);
    k_final<<<EE / 8, 256>>>(x, uu, rcv, Wout, out);
}

// round 5
// speedup vs baseline: 2.0103x; 2.0103x over previous
#include <cuda_runtime.h>
#include <math.h>
#include <cstdint>

#define NN 8192
#define EE 131072

// ---------------- scratch (device globals; no allocations allowed) ----------------
__device__ __align__(16) float g_featp[EE * 64];   // bessel+attrs, padded K 40->64
__device__ __align__(16) float g_u[EE];
__device__ __align__(16) float g_Y[EE * 16];
__device__ __align__(16) float g_x[EE * 256];
__device__ __align__(16) float g_t[EE * 256];
__device__ __align__(16) float g_s16[EE * 16];
__device__ __align__(16) float g_V[EE * 256];
__device__ __align__(16) float g_VV0p[EE * 32];    // VV[:, :, 0] padded 16->32
__device__ __align__(16) float g_wY[NN * 256];
__device__ __align__(16) float g_Bt[360448];       // padded + tf32-rounded weights

// ---------------- helpers ----------------
__device__ __forceinline__ float tf32r(float v) {
    uint32_t r;
    asm("cvt.rna.tf32.f32 %0, %1;" : "=r"(r) : "f"(v));
    return __uint_as_float(r);
}
__device__ __forceinline__ uint32_t smem_u32(const void* p) {
    uint32_t a;
    asm("{ .reg .u64 t; cvta.to.shared.u64 t, %1; cvt.u32.u64 %0, t; }" : "=r"(a) : "l"(p));
    return a;
}
__device__ __forceinline__ void cp16(uint32_t dst, const void* src) {
    asm volatile("cp.async.cg.shared.global [%0], [%1], 16;" :: "r"(dst), "l"(src));
}
#define CP_COMMIT() asm volatile("cp.async.commit_group;" ::: "memory")
#define CP_WAIT(n)  asm volatile("cp.async.wait_group %0;" :: "n"(n) : "memory")

__device__ __forceinline__ void mma8(float* d, const uint32_t* a, const uint32_t* b) {
    asm volatile(
        "mma.sync.aligned.m16n8k8.row.col.f32.tf32.tf32.f32 "
        "{%0,%1,%2,%3}, {%4,%5,%6,%7}, {%8,%9}, {%0,%1,%2,%3};"
        : "+f"(d[0]), "+f"(d[1]), "+f"(d[2]), "+f"(d[3])
        : "r"(a[0]), "r"(a[1]), "r"(a[2]), "r"(a[3]), "r"(b[0]), "r"(b[1]));
}

__device__ __forceinline__ float silu_f(float t) { return t / (1.0f + __expf(-t)); }

// smem layout (floats): A pad 36/row, B pad 136/row
static constexpr int APAD = 36;
static constexpr int BPAD = 136;
static constexpr int SM_A0 = 0;
static constexpr int SM_A1 = 128 * APAD;                 // 4608
static constexpr int SM_B0 = SM_A1 + 128 * APAD;         // 9216
static constexpr int SM_B1 = SM_B0 + 32 * BPAD;          // 13568
static constexpr int SM_FLOATS = SM_B1 + 32 * BPAD;      // 17920 floats = 71680 B

// ---------------- mma.sync tf32 GEMM: C[E,256] = A[E,K] @ B[K,256] ----------------
// EPI: 1 = silu, 2 = u*silu, 3 = C = (C + u*silu)/sqrt(2).  All outputs tf32-rounded.
template<int EPI>
__global__ __launch_bounds__(256) void mgemm(
    const float* __restrict__ A1, int sA1, int ntA1,   // main A source, stride, #k-tiles
    const float* __restrict__ A2,                      // stride-32 tail source or null
    const float* __restrict__ B, int nt,               // padded weights [nt*32, 256]
    const float* __restrict__ bias, const float* __restrict__ u,
    float* __restrict__ C)
{
    extern __shared__ float smf[];
    uint32_t sb = smem_u32(smf);
    int tid = threadIdx.x, lane = tid & 31, wid = tid >> 5;
    int warp_m = wid & 1, warp_n = wid >> 1;
    int rowBase = blockIdx.x * 128;
    int colBase = blockIdx.y * 128;

    // ---- async tile loader ----
    auto load_tile = [&](int kt, int buf) {
        // A: 128 rows x 32 k
        const float* Ap;
        int stride;
        if (kt < ntA1) { Ap = A1 + (size_t)rowBase * sA1 + kt * 32; stride = sA1; }
        else           { Ap = A2 + (size_t)rowBase * 32;            stride = 32;  }
        uint32_t aBase = sb + (buf ? SM_A1 : SM_A0) * 4;
        #pragma unroll
        for (int i = 0; i < 4; i++) {
            int f = tid + i * 256;
            int r = f >> 3, q = f & 7;
            cp16(aBase + (r * APAD + q * 4) * 4, Ap + (size_t)r * stride + q * 4);
        }
        // B: 32 k x 128 cols (source row stride 256)
        const float* Bp = B + (size_t)kt * 32 * 256 + colBase;
        uint32_t bBase = sb + (buf ? SM_B1 : SM_B0) * 4;
        #pragma unroll
        for (int i = 0; i < 4; i++) {
            int f = tid + i * 256;
            int k = f >> 5, q = f & 31;
            cp16(bBase + (k * BPAD + q * 4) * 4, Bp + (size_t)k * 256 + q * 4);
        }
        CP_COMMIT();
    };

    float acc[4][4][4];
    #pragma unroll
    for (int i = 0; i < 4; i++)
        #pragma unroll
        for (int j = 0; j < 4; j++)
            #pragma unroll
            for (int q = 0; q < 4; q++) acc[i][j][q] = 0.f;

    load_tile(0, 0);

    for (int kt = 0; kt < nt; kt++) {
        if (kt + 1 < nt) { load_tile(kt + 1, (kt + 1) & 1); CP_WAIT(1); }
        else             { CP_WAIT(0); }
        __syncthreads();

        const float* As = smf + ((kt & 1) ? SM_A1 : SM_A0);
        const float* Bs = smf + ((kt & 1) ? SM_B1 : SM_B0);
        #pragma unroll
        for (int s = 0; s < 4; s++) {
            uint32_t a[4][4], b[4][2];
            int r1 = lane >> 2, c1 = s * 8 + (lane & 3);
            #pragma unroll
            for (int i = 0; i < 4; i++) {
                int rb = warp_m * 64 + i * 16 + r1;
                a[i][0] = __float_as_uint(As[rb * APAD + c1]);
                a[i][1] = __float_as_uint(As[(rb + 8) * APAD + c1]);
                a[i][2] = __float_as_uint(As[rb * APAD + c1 + 4]);
                a[i][3] = __float_as_uint(As[(rb + 8) * APAD + c1 + 4]);
            }
            int kb = s * 8 + (lane & 3), nq = lane >> 2;
            #pragma unroll
            for (int j = 0; j < 4; j++) {
                int cb = warp_n * 32 + j * 8 + nq;
                b[j][0] = __float_as_uint(Bs[kb * BPAD + cb]);
                b[j][1] = __float_as_uint(Bs[(kb + 4) * BPAD + cb]);
            }
            #pragma unroll
            for (int i = 0; i < 4; i++)
                #pragma unroll
                for (int j = 0; j < 4; j++)
                    mma8(acc[i][j], a[i], b[j]);
        }
        __syncthreads();
    }

    // ---- fused epilogue ----
    const float RS2 = 0.7071067811865476f;
    #pragma unroll
    for (int i = 0; i < 4; i++) {
        int ra = rowBase + warp_m * 64 + i * 16 + (lane >> 2);
        int rb = ra + 8;
        float ua = 0.f, ub = 0.f;
        if (EPI >= 2) { ua = u[ra]; ub = u[rb]; }
        #pragma unroll
        for (int j = 0; j < 4; j++) {
            int col = colBase + warp_n * 32 + j * 8 + 2 * (lane & 3);
            float b0 = __ldg(bias + col), b1 = __ldg(bias + col + 1);
            float t0 = acc[i][j][0] + b0, t1 = acc[i][j][1] + b1;
            float t2 = acc[i][j][2] + b0, t3 = acc[i][j][3] + b1;
            float o0, o1, o2, o3;
            if (EPI == 1) {
                o0 = silu_f(t0); o1 = silu_f(t1); o2 = silu_f(t2); o3 = silu_f(t3);
            } else {
                o0 = ua * silu_f(t0); o1 = ua * silu_f(t1);
                o2 = ub * silu_f(t2); o3 = ub * silu_f(t3);
            }
            float* pa = C + (size_t)ra * 256 + col;
            float* pb = C + (size_t)rb * 256 + col;
            if (EPI == 3) {
                float2 oa = *(const float2*)pa;
                float2 ob = *(const float2*)pb;
                o0 = (oa.x + o0) * RS2; o1 = (oa.y + o1) * RS2;
                o2 = (ob.x + o2) * RS2; o3 = (ob.y + o3) * RS2;
            }
            *(float2*)pa = make_float2(tf32r(o0), tf32r(o1));
            *(float2*)pb = make_float2(tf32r(o2), tf32r(o3));
        }
    }
}

// ---------------- weight pad+round: Bt[k, n] = tf32(W[k, n]), k >= K -> 0 -------------
__global__ void k_wprep(const float* __restrict__ W, float* __restrict__ Bt, int K)
{
    int idx = blockIdx.x * 256 + threadIdx.x;
    int k = idx >> 8;
    Bt[idx] = (k < K) ? tf32r(W[idx]) : 0.f;
}

// ---------------- geometry ----------------
__global__ void k_geom(const float* __restrict__ vec, const float* __restrict__ attrs,
                       const int* __restrict__ snd, const int* __restrict__ rcv,
                       float* __restrict__ feat, float* __restrict__ uo, float* __restrict__ Yo)
{
    int e = blockIdx.x * blockDim.x + threadIdx.x;
    if (e >= EE) return;
    float vx = vec[3*e+0], vy = vec[3*e+1], vz = vec[3*e+2];
    float d2 = vx*vx + vy*vy + vz*vz;
    float d  = sqrtf(d2);
    float d6 = d2 * d2 * d2;
    float env = 1.0f + d6 * (-28.0f + d * (48.0f - 21.0f * d));
    uo[e] = env;
    float invd = 1.0f / d;
    const float S2 = 1.4142135623730951f;
    float* fp = feat + (size_t)e * 64;
    #pragma unroll
    for (int k = 1; k <= 8; k++)
        fp[k-1] = tf32r(S2 * sinpif((float)k * d) * invd);
    int s = snd[e], r = rcv[e];
    #pragma unroll
    for (int i = 0; i < 16; i++) fp[8 + i]  = tf32r(attrs[s*16 + i]);
    #pragma unroll
    for (int i = 0; i < 16; i++) fp[24 + i] = tf32r(attrs[r*16 + i]);
    #pragma unroll
    for (int i = 40; i < 64; i++) fp[i] = 0.f;

    float x = vx*invd, y = vy*invd, z = vz*invd;
    const float s3  = 1.7320508075688772f;
    const float s5  = 2.2360679774997896f;
    const float s15 = 3.8729833462074170f;
    const float s7  = 2.6457513110645907f;
    const float c33 = 2.0916500663351885f;
    const float c32 = 10.246950765959598f;
    const float c31 = 1.6201851746019649f;
    float* Yp = Yo + (size_t)e * 16;
    Yp[0]  = 1.0f;
    Yp[1]  = s3 * x;  Yp[2]  = s3 * y;  Yp[3]  = s3 * z;
    Yp[4]  = s15 * x * y;  Yp[5]  = s15 * y * z;
    Yp[6]  = 0.5f * s5 * (3.0f*z*z - 1.0f);
    Yp[7]  = s15 * x * z;
    Yp[8]  = 0.5f * s15 * (x*x - y*y);
    Yp[9]  = c33 * y * (3.0f*x*x - y*y);
    Yp[10] = c32 * x * y * z;
    Yp[11] = c31 * y * (5.0f*z*z - 1.0f);
    Yp[12] = 0.5f * s7 * (5.0f*z*z*z - 3.0f*z);
    Yp[13] = c31 * x * (5.0f*z*z - 1.0f);
    Yp[14] = 0.5f * c32 * z * (x*x - y*y);
    Yp[15] = c33 * x * (x*x - 3.0f*y*y);
}

// ---------------- (E,256) @ (256,16): thread-per-edge, W broadcast from smem ----------
__global__ __launch_bounds__(128) void gemm_n16(const float* __restrict__ X,
                                                const float* __restrict__ W,
                                                float* __restrict__ S)
{
    __shared__ __align__(16) float Ws[4096];
    int tid = threadIdx.x;
    #pragma unroll
    for (int i = 0; i < 8; i++)
        ((float4*)Ws)[tid + i * 128] = ((const float4*)W)[tid + i * 128];
    __syncthreads();
    size_t e = (size_t)blockIdx.x * 128 + tid;
    const float4* xr = (const float4*)(X + e * 256);
    float acc[16];
    #pragma unroll
    for (int c = 0; c < 16; c++) acc[c] = 0.f;
    #pragma unroll 4
    for (int k4 = 0; k4 < 64; k4++) {
        float4 xv = xr[k4];
        float xs[4] = {xv.x, xv.y, xv.z, xv.w};
        #pragma unroll
        for (int j = 0; j < 4; j++) {
            const float4* wr = (const float4*)&Ws[(k4 * 4 + j) * 16];
            #pragma unroll
            for (int q = 0; q < 4; q++) {
                float4 w = wr[q];
                acc[q*4+0] += xs[j] * w.x;
                acc[q*4+1] += xs[j] * w.y;
                acc[q*4+2] += xs[j] * w.z;
                acc[q*4+3] += xs[j] * w.w;
            }
        }
    }
    float4* sp = (float4*)(S + e * 16);
    #pragma unroll
    for (int q = 0; q < 4; q++)
        sp[q] = make_float4(acc[q*4], acc[q*4+1], acc[q*4+2], acc[q*4+3]);
}

// ---------------- V[e,m,:] = xv[e,m] * Y[e,:] ----------------
__global__ void k_buildV(const float* __restrict__ xv, const float* __restrict__ Y,
                         float* __restrict__ V)
{
    int idx = blockIdx.x * blockDim.x + threadIdx.x;
    float w = xv[idx];
    int e = idx >> 4;
    const float4* Y4 = (const float4*)(Y + (size_t)e * 16);
    float4* V4 = (float4*)(V + (size_t)idx * 16);
    #pragma unroll
    for (int q = 0; q < 4; q++) {
        float4 y = Y4[q];
        V4[q] = make_float4(w*y.x, w*y.y, w*y.z, w*y.w);
    }
}

__global__ void k_zero4(float4* p, int n4)
{
    int i = blockIdx.x * blockDim.x + threadIdx.x;
    if (i < n4) p[i] = make_float4(0.f, 0.f, 0.f, 0.f);
}

// ---------------- segment_sum scatter ----------------
__global__ void k_scatter(const float* __restrict__ w, const float* __restrict__ Y,
                          const int* __restrict__ snd, float* __restrict__ wY)
{
    int idx = blockIdx.x * blockDim.x + threadIdx.x;
    int e = idx >> 4, m = idx & 15;
    float wv = w[idx];
    int s = snd[e];
    float* base = wY + (size_t)s * 256 + m * 16;
    const float4* Y4 = (const float4*)(Y + (size_t)e * 16);
    #pragma unroll
    for (int q = 0; q < 4; q++) {
        float4 y = Y4[q];
        atomicAdd(base + q*4 + 0, wv * y.x);
        atomicAdd(base + q*4 + 1, wv * y.y);
        atomicAdd(base + q*4 + 2, wv * y.z);
        atomicAdd(base + q*4 + 3, wv * y.w);
    }
}

// ---------------- per-(e,m) update ----------------
__global__ __launch_bounds__(256)
void k_update(const int* __restrict__ snd, const float* __restrict__ wY,
              float* __restrict__ V, float* __restrict__ VV0p, const float* __restrict__ Wlsh)
{
    __shared__ float Wsh[256];
    int tid = threadIdx.x;
    Wsh[tid] = Wlsh[tid];
    __syncthreads();
    int idx = blockIdx.x * 256 + tid;
    int e = idx >> 4, m = idx & 15;
    int s = snd[e];
    const float4* wyp = (const float4*)(wY + (size_t)s * 256 + m * 16);
    float4* vp = (float4*)(V + (size_t)idx * 16);
    float vv[16];
    #pragma unroll
    for (int q = 0; q < 4; q++) {
        float4 a = wyp[q];
        float4 b = vp[q];
        vv[q*4+0] = 0.25f * a.x * b.x;
        vv[q*4+1] = 0.25f * a.y * b.y;
        vv[q*4+2] = 0.25f * a.z * b.z;
        vv[q*4+3] = 0.25f * a.w * b.w;
    }
    VV0p[(size_t)e * 32 + m] = tf32r(vv[0]);
    VV0p[(size_t)e * 32 + 16 + m] = 0.f;
    float o[16];
    #pragma unroll
    for (int j = 0; j < 16; j++) o[j] = 0.f;
    #pragma unroll
    for (int i = 0; i < 16; i++) {
        float t = vv[i];
        #pragma unroll
        for (int j = 0; j < 16; j++) o[j] += t * Wsh[i * 16 + j];
    }
    #pragma unroll
    for (int q = 0; q < 4; q++)
        vp[q] = make_float4(o[q*4], o[q*4+1], o[q*4+2], o[q*4+3]);
}

// ---------------- final readout ----------------
__global__ __launch_bounds__(256)
void k_final(const float* __restrict__ x, const float* __restrict__ u,
             const int* __restrict__ rcv, const float* __restrict__ Wout,
             float* __restrict__ out)
{
    __shared__ float Wo[256];
    int tid = threadIdx.x;
    Wo[tid] = Wout[tid];
    __syncthreads();
    int warp = tid >> 5, lane = tid & 31;
    size_t e = (size_t)blockIdx.x * 8 + warp;
    float p = 0.f;
    #pragma unroll
    for (int k = lane; k < 256; k += 32)
        p += x[e * 256 + k] * Wo[k];
    #pragma unroll
    for (int off = 16; off; off >>= 1)
        p += __shfl_xor_sync(0xffffffffu, p, off);
    if (lane == 0)
        atomicAdd(&out[rcv[e]], p * u[e] * 0.25f);
}

// ---------------- host ----------------
extern "C" void kernel_launch(void* const* d_in, const int* in_sizes, int n_in,
                              void* d_out, int out_size)
{
    const float* attrs = (const float*)d_in[0];
    const float* vec   = (const float*)d_in[1];
    const int*   snd   = (const int*)d_in[2];
    const int*   rcv   = (const int*)d_in[3];
    const float* We0   = (const float*)d_in[4];
    const float* be0   = (const float*)d_in[5];
    const float* We1   = (const float*)d_in[6];
    const float* be1   = (const float*)d_in[7];
    const float* Wv0   = (const float*)d_in[8];
    const float* Wlw   = (const float*)d_in[9];
    const float* Wlsh  = (const float*)d_in[10];
    const float* Wly1  = (const float*)d_in[11];
    const float* bly1  = (const float*)d_in[12];
    const float* Wly2  = (const float*)d_in[13];
    const float* bly2  = (const float*)d_in[14];
    const float* Wout  = (const float*)d_in[15];
    float* out = (float*)d_out;

    float *featp, *uu, *Y, *x, *t, *s16, *V, *VV0p, *wY, *Bt;
    cudaGetSymbolAddress((void**)&featp, g_featp);
    cudaGetSymbolAddress((void**)&uu,    g_u);
    cudaGetSymbolAddress((void**)&Y,     g_Y);
    cudaGetSymbolAddress((void**)&x,     g_x);
    cudaGetSymbolAddress((void**)&t,     g_t);
    cudaGetSymbolAddress((void**)&s16,   g_s16);
    cudaGetSymbolAddress((void**)&V,     g_V);
    cudaGetSymbolAddress((void**)&VV0p,  g_VV0p);
    cudaGetSymbolAddress((void**)&wY,    g_wY);
    cudaGetSymbolAddress((void**)&Bt,    g_Bt);

    // padded+rounded weight regions [Kp][256]
    float* Bt_e0  = Bt + 0;        // Kp=64
    float* Bt_e1  = Bt + 16384;    // Kp=256
    float* Bt_l10 = Bt + 81920;    // Kp=288
    float* Bt_l11 = Bt + 155648;   // Kp=288
    float* Bt_l20 = Bt + 229376;   // Kp=256
    float* Bt_l21 = Bt + 294912;   // Kp=256

    const int SMEM_BYTES = SM_FLOATS * 4;   // 71680
    cudaFuncSetAttribute(mgemm<1>, cudaFuncAttributeMaxDynamicSharedMemorySize, SMEM_BYTES);
    cudaFuncSetAttribute(mgemm<2>, cudaFuncAttributeMaxDynamicSharedMemorySize, SMEM_BYTES);
    cudaFuncSetAttribute(mgemm<3>, cudaFuncAttributeMaxDynamicSharedMemorySize, SMEM_BYTES);

    // weight prep (pad + tf32 round)
    k_wprep<<<64, 256>>>(We0, Bt_e0, 40);
    k_wprep<<<256, 256>>>(We1, Bt_e1, 256);
    k_wprep<<<288, 256>>>(Wly1, Bt_l10, 272);
    k_wprep<<<288, 256>>>(Wly1 + 272 * 256, Bt_l11, 272);
    k_wprep<<<256, 256>>>(Wly2, Bt_l20, 256);
    k_wprep<<<256, 256>>>(Wly2 + 256 * 256, Bt_l21, 256);

    k_geom<<<EE / 256, 256>>>(vec, attrs, snd, rcv, featp, uu, Y);

    dim3 gg(EE / 128, 2);
    mgemm<1><<<gg, 256, SMEM_BYTES>>>(featp, 64, 2, nullptr, Bt_e0, 2, be0, nullptr, t);
    mgemm<2><<<gg, 256, SMEM_BYTES>>>(t, 256, 8, nullptr, Bt_e1, 8, be1, uu, x);

    gemm_n16<<<EE / 128, 128>>>(x, Wv0, s16);
    k_buildV<<<EE * 16 / 256, 256>>>(s16, Y, V);

    for (int l = 0; l < 2; l++) {
        gemm_n16<<<EE / 128, 128>>>(x, Wlw + (size_t)l * 256 * 16, s16);
        k_zero4<<<(NN * 256 / 4 + 255) / 256, 256>>>((float4*)wY, NN * 256 / 4);
        k_scatter<<<EE * 16 / 256, 256>>>(s16, Y, snd, wY);
        k_update<<<EE * 16 / 256, 256>>>(snd, wY, V, VV0p, Wlsh + (size_t)l * 256);
        mgemm<1><<<gg, 256, SMEM_BYTES>>>(x, 256, 8, VV0p,
                                          (l == 0) ? Bt_l10 : Bt_l11, 9,
                                          bly1 + (size_t)l * 256, nullptr, t);
        mgemm<3><<<gg, 256, SMEM_BYTES>>>(t, 256, 8, nullptr,
                                          (l == 0) ? Bt_l20 : Bt_l21, 8,
                                          bly2 + (size_t)l * 256, uu, x);
    }

    k_zero4<<<(NN / 4 + 255) / 256, 256>>>((float4*)out, NN / 4);
    k_final<<<EE / 8, 256>>>(x, uu, rcv, Wout, out);
}

// round 6
// speedup vs baseline: 2.6040x; 1.2953x over previous
#include <cuda_runtime.h>
#include <math.h>
#include <cstdint>

#define NN 8192
#define EE 131072

// ---------------- scratch (device globals; no allocations allowed) ----------------
__device__ __align__(16) float g_featp[EE * 64];   // bessel+attrs, padded K 40->64
__device__ __align__(16) float g_u[EE];
__device__ __align__(16) float g_Y[EE * 16];
__device__ __align__(16) float g_x[EE * 256];
__device__ __align__(16) float g_t[EE * 256];
__device__ __align__(16) float g_s16[EE * 16];
__device__ __align__(16) float g_V[EE * 256];
__device__ __align__(16) float g_VV0p[EE * 32];    // VV[:, :, 0] padded 16->32
__device__ __align__(16) float g_wY[NN * 256];
__device__ __align__(16) float g_Bt[360448];       // transposed [N][Kp] tf32 weights

// ---------------- helpers ----------------
__device__ __forceinline__ float tf32r(float v) {
    uint32_t r;
    asm("cvt.rna.tf32.f32 %0, %1;" : "=r"(r) : "f"(v));
    return __uint_as_float(r);
}
__device__ __forceinline__ uint32_t smem_u32(const void* p) {
    uint32_t a;
    asm("{ .reg .u64 t; cvta.to.shared.u64 t, %1; cvt.u32.u64 %0, t; }" : "=r"(a) : "l"(p));
    return a;
}
__device__ __forceinline__ void cp16(uint32_t dst, const void* src) {
    asm volatile("cp.async.cg.shared.global [%0], [%1], 16;" :: "r"(dst), "l"(src));
}
#define CP_COMMIT() asm volatile("cp.async.commit_group;" ::: "memory")
#define CP_WAIT(n)  asm volatile("cp.async.wait_group %0;" :: "n"(n) : "memory")

__device__ __forceinline__ void mma8(float* d, const uint32_t* a, const uint32_t* b) {
    asm volatile(
        "mma.sync.aligned.m16n8k8.row.col.f32.tf32.tf32.f32 "
        "{%0,%1,%2,%3}, {%4,%5,%6,%7}, {%8,%9}, {%0,%1,%2,%3};"
        : "+f"(d[0]), "+f"(d[1]), "+f"(d[2]), "+f"(d[3])
        : "r"(a[0]), "r"(a[1]), "r"(a[2]), "r"(a[3]), "r"(b[0]), "r"(b[1]));
}

__device__ __forceinline__ float silu_f(float t) { return t / (1.0f + __expf(-t)); }

// smem layout (floats): A[128][36], Bt[256][36] per stage, 3 stages
static constexpr int APAD = 36;
static constexpr int BPADT = 36;
static constexpr int STG_A = 128 * APAD;                  // 4608
static constexpr int STG_B = 256 * BPADT;                 // 9216
static constexpr int STG_FLOATS = STG_A + STG_B;          // 13824
static constexpr int SM_FLOATS = 3 * STG_FLOATS;          // 41472 (165888 B)

// ---------------- mma.sync tf32 GEMM: C[E,256] = A[E,K] @ B[K,256] ----------------
// One CTA computes a full 128x256 tile.  B is pre-transposed [256][Kp].
// EPI: 1 = silu, 2 = u*silu, 3 = C = (C + u*silu)/sqrt(2).  Outputs tf32-rounded.
template<int EPI>
__global__ __launch_bounds__(256, 1) void mgemm(
    const float* __restrict__ A1, int sA1, int ntA1,   // main A source, stride, #k-tiles
    const float* __restrict__ A2,                      // stride-32 tail source or null
    const float* __restrict__ Bt, int Kp, int nt,      // transposed weights [256][Kp]
    const float* __restrict__ bias, const float* __restrict__ u,
    float* __restrict__ C)
{
    extern __shared__ float smf[];
    uint32_t sb = smem_u32(smf);
    int tid = threadIdx.x, lane = tid & 31, wid = tid >> 5;
    int warp_m = wid & 1, warp_n = wid >> 1;     // 2 x 4 warp grid, 64x64 warp tile
    int rowBase = blockIdx.x * 128;

    // ---- async tile loader ----
    auto load_tile = [&](int kt, int buf) {
        uint32_t stBase = sb + buf * STG_FLOATS * 4;
        // A: 128 rows x 32 k  -> As[r][k], row pad 36
        const float* Ap;
        int stride;
        if (kt < ntA1) { Ap = A1 + (size_t)rowBase * sA1 + kt * 32; stride = sA1; }
        else           { Ap = A2 + (size_t)rowBase * 32;            stride = 32;  }
        #pragma unroll
        for (int i = 0; i < 4; i++) {
            int f = tid + i * 256;
            int r = f >> 3, q = f & 7;
            cp16(stBase + (r * APAD + q * 4) * 4, Ap + (size_t)r * stride + q * 4);
        }
        // B: 256 n-rows x 32 k  -> Bs[n][k], row pad 36  (source row stride Kp)
        const float* Bp = Bt + kt * 32;
        uint32_t bBase = stBase + STG_A * 4;
        #pragma unroll
        for (int i = 0; i < 8; i++) {
            int f = tid + i * 256;
            int n = f >> 3, q = f & 7;
            cp16(bBase + (n * BPADT + q * 4) * 4, Bp + (size_t)n * Kp + q * 4);
        }
        CP_COMMIT();
    };

    float acc[4][8][4];
    #pragma unroll
    for (int i = 0; i < 4; i++)
        #pragma unroll
        for (int j = 0; j < 8; j++)
            #pragma unroll
            for (int q = 0; q < 4; q++) acc[i][j][q] = 0.f;

    load_tile(0, 0);
    if (nt > 1) load_tile(1, 1);

    for (int kt = 0; kt < nt; kt++) {
        if (kt + 1 < nt) CP_WAIT(1); else CP_WAIT(0);
        __syncthreads();

        const float* As = smf + (kt % 3) * STG_FLOATS;
        const float* Bs = As + STG_A;
        #pragma unroll
        for (int s = 0; s < 4; s++) {
            uint32_t a[4][4], b[8][2];
            int r1 = lane >> 2, c1 = s * 8 + (lane & 3);
            #pragma unroll
            for (int i = 0; i < 4; i++) {
                int rb = warp_m * 64 + i * 16 + r1;
                a[i][0] = __float_as_uint(As[rb * APAD + c1]);
                a[i][1] = __float_as_uint(As[(rb + 8) * APAD + c1]);
                a[i][2] = __float_as_uint(As[rb * APAD + c1 + 4]);
                a[i][3] = __float_as_uint(As[(rb + 8) * APAD + c1 + 4]);
            }
            int kb = s * 8 + (lane & 3), nq = lane >> 2;
            #pragma unroll
            for (int j = 0; j < 8; j++) {
                int cb = warp_n * 64 + j * 8 + nq;
                b[j][0] = __float_as_uint(Bs[cb * BPADT + kb]);
                b[j][1] = __float_as_uint(Bs[cb * BPADT + kb + 4]);
            }
            #pragma unroll
            for (int i = 0; i < 4; i++)
                #pragma unroll
                for (int j = 0; j < 8; j++)
                    mma8(acc[i][j], a[i], b[j]);
        }
        __syncthreads();
        if (kt + 2 < nt) load_tile(kt + 2, (kt + 2) % 3);
    }

    // ---- fused epilogue ----
    const float RS2 = 0.7071067811865476f;
    #pragma unroll
    for (int i = 0; i < 4; i++) {
        int ra = rowBase + warp_m * 64 + i * 16 + (lane >> 2);
        int rb = ra + 8;
        float ua = 0.f, ub = 0.f;
        if (EPI >= 2) { ua = u[ra]; ub = u[rb]; }
        #pragma unroll
        for (int j = 0; j < 8; j++) {
            int col = warp_n * 64 + j * 8 + 2 * (lane & 3);
            float b0 = __ldg(bias + col), b1 = __ldg(bias + col + 1);
            float t0 = acc[i][j][0] + b0, t1 = acc[i][j][1] + b1;
            float t2 = acc[i][j][2] + b0, t3 = acc[i][j][3] + b1;
            float o0, o1, o2, o3;
            if (EPI == 1) {
                o0 = silu_f(t0); o1 = silu_f(t1); o2 = silu_f(t2); o3 = silu_f(t3);
            } else {
                o0 = ua * silu_f(t0); o1 = ua * silu_f(t1);
                o2 = ub * silu_f(t2); o3 = ub * silu_f(t3);
            }
            float* pa = C + (size_t)ra * 256 + col;
            float* pb = C + (size_t)rb * 256 + col;
            if (EPI == 3) {
                float2 oa = *(const float2*)pa;
                float2 ob = *(const float2*)pb;
                o0 = (oa.x + o0) * RS2; o1 = (oa.y + o1) * RS2;
                o2 = (ob.x + o2) * RS2; o3 = (ob.y + o3) * RS2;
            }
            *(float2*)pa = make_float2(tf32r(o0), tf32r(o1));
            *(float2*)pb = make_float2(tf32r(o2), tf32r(o3));
        }
    }
}

// ---------------- weight transpose+pad+round: Bt[n, k] = tf32(W[k, n]) ----------------
__global__ void k_wprep(const float* __restrict__ W, float* __restrict__ Bt, int K, int Kp)
{
    int idx = blockIdx.x * 256 + threadIdx.x;     // 256*Kp total
    int n = idx / Kp, k = idx % Kp;
    Bt[idx] = (k < K) ? tf32r(W[(size_t)k * 256 + n]) : 0.f;
}

// ---------------- geometry ----------------
__global__ void k_geom(const float* __restrict__ vec, const float* __restrict__ attrs,
                       const int* __restrict__ snd, const int* __restrict__ rcv,
                       float* __restrict__ feat, float* __restrict__ uo, float* __restrict__ Yo)
{
    int e = blockIdx.x * blockDim.x + threadIdx.x;
    if (e >= EE) return;
    float vx = vec[3*e+0], vy = vec[3*e+1], vz = vec[3*e+2];
    float d2 = vx*vx + vy*vy + vz*vz;
    float d  = sqrtf(d2);
    float d6 = d2 * d2 * d2;
    float env = 1.0f + d6 * (-28.0f + d * (48.0f - 21.0f * d));
    uo[e] = env;
    float invd = 1.0f / d;
    const float S2 = 1.4142135623730951f;
    float* fp = feat + (size_t)e * 64;
    #pragma unroll
    for (int k = 1; k <= 8; k++)
        fp[k-1] = tf32r(S2 * sinpif((float)k * d) * invd);
    int s = snd[e], r = rcv[e];
    #pragma unroll
    for (int i = 0; i < 16; i++) fp[8 + i]  = tf32r(attrs[s*16 + i]);
    #pragma unroll
    for (int i = 0; i < 16; i++) fp[24 + i] = tf32r(attrs[r*16 + i]);
    #pragma unroll
    for (int i = 40; i < 64; i++) fp[i] = 0.f;

    float x = vx*invd, y = vy*invd, z = vz*invd;
    const float s3  = 1.7320508075688772f;
    const float s5  = 2.2360679774997896f;
    const float s15 = 3.8729833462074170f;
    const float s7  = 2.6457513110645907f;
    const float c33 = 2.0916500663351885f;
    const float c32 = 10.246950765959598f;
    const float c31 = 1.6201851746019649f;
    float* Yp = Yo + (size_t)e * 16;
    Yp[0]  = 1.0f;
    Yp[1]  = s3 * x;  Yp[2]  = s3 * y;  Yp[3]  = s3 * z;
    Yp[4]  = s15 * x * y;  Yp[5]  = s15 * y * z;
    Yp[6]  = 0.5f * s5 * (3.0f*z*z - 1.0f);
    Yp[7]  = s15 * x * z;
    Yp[8]  = 0.5f * s15 * (x*x - y*y);
    Yp[9]  = c33 * y * (3.0f*x*x - y*y);
    Yp[10] = c32 * x * y * z;
    Yp[11] = c31 * y * (5.0f*z*z - 1.0f);
    Yp[12] = 0.5f * s7 * (5.0f*z*z*z - 3.0f*z);
    Yp[13] = c31 * x * (5.0f*z*z - 1.0f);
    Yp[14] = 0.5f * c32 * z * (x*x - y*y);
    Yp[15] = c33 * x * (x*x - 3.0f*y*y);
}

// ---------------- (E,256) @ (256,16): thread-per-edge, W broadcast from smem ----------
__global__ __launch_bounds__(128) void gemm_n16(const float* __restrict__ X,
                                                const float* __restrict__ W,
                                                float* __restrict__ S)
{
    __shared__ __align__(16) float Ws[4096];
    int tid = threadIdx.x;
    #pragma unroll
    for (int i = 0; i < 8; i++)
        ((float4*)Ws)[tid + i * 128] = ((const float4*)W)[tid + i * 128];
    __syncthreads();
    size_t e = (size_t)blockIdx.x * 128 + tid;
    const float4* xr = (const float4*)(X + e * 256);
    float acc[16];
    #pragma unroll
    for (int c = 0; c < 16; c++) acc[c] = 0.f;
    #pragma unroll 4
    for (int k4 = 0; k4 < 64; k4++) {
        float4 xv = xr[k4];
        float xs[4] = {xv.x, xv.y, xv.z, xv.w};
        #pragma unroll
        for (int j = 0; j < 4; j++) {
            const float4* wr = (const float4*)&Ws[(k4 * 4 + j) * 16];
            #pragma unroll
            for (int q = 0; q < 4; q++) {
                float4 w = wr[q];
                acc[q*4+0] += xs[j] * w.x;
                acc[q*4+1] += xs[j] * w.y;
                acc[q*4+2] += xs[j] * w.z;
                acc[q*4+3] += xs[j] * w.w;
            }
        }
    }
    float4* sp = (float4*)(S + e * 16);
    #pragma unroll
    for (int q = 0; q < 4; q++)
        sp[q] = make_float4(acc[q*4], acc[q*4+1], acc[q*4+2], acc[q*4+3]);
}

// ---------------- V[e,m,:] = xv[e,m] * Y[e,:] ----------------
__global__ void k_buildV(const float* __restrict__ xv, const float* __restrict__ Y,
                         float* __restrict__ V)
{
    int idx = blockIdx.x * blockDim.x + threadIdx.x;
    float w = xv[idx];
    int e = idx >> 4;
    const float4* Y4 = (const float4*)(Y + (size_t)e * 16);
    float4* V4 = (float4*)(V + (size_t)idx * 16);
    #pragma unroll
    for (int q = 0; q < 4; q++) {
        float4 y = Y4[q];
        V4[q] = make_float4(w*y.x, w*y.y, w*y.z, w*y.w);
    }
}

__global__ void k_zero4(float4* p, int n4)
{
    int i = blockIdx.x * blockDim.x + threadIdx.x;
    if (i < n4) p[i] = make_float4(0.f, 0.f, 0.f, 0.f);
}

// ---------------- segment_sum scatter ----------------
__global__ void k_scatter(const float* __restrict__ w, const float* __restrict__ Y,
                          const int* __restrict__ snd, float* __restrict__ wY)
{
    int idx = blockIdx.x * blockDim.x + threadIdx.x;
    int e = idx >> 4, m = idx & 15;
    float wv = w[idx];
    int s = snd[e];
    float* base = wY + (size_t)s * 256 + m * 16;
    const float4* Y4 = (const float4*)(Y + (size_t)e * 16);
    #pragma unroll
    for (int q = 0; q < 4; q++) {
        float4 y = Y4[q];
        atomicAdd(base + q*4 + 0, wv * y.x);
        atomicAdd(base + q*4 + 1, wv * y.y);
        atomicAdd(base + q*4 + 2, wv * y.z);
        atomicAdd(base + q*4 + 3, wv * y.w);
    }
}

// ---------------- per-(e,m) update ----------------
__global__ __launch_bounds__(256)
void k_update(const int* __restrict__ snd, const float* __restrict__ wY,
              float* __restrict__ V, float* __restrict__ VV0p, const float* __restrict__ Wlsh)
{
    __shared__ float Wsh[256];
    int tid = threadIdx.x;
    Wsh[tid] = Wlsh[tid];
    __syncthreads();
    int idx = blockIdx.x * 256 + tid;
    int e = idx >> 4, m = idx & 15;
    int s = snd[e];
    const float4* wyp = (const float4*)(wY + (size_t)s * 256 + m * 16);
    float4* vp = (float4*)(V + (size_t)idx * 16);
    float vv[16];
    #pragma unroll
    for (int q = 0; q < 4; q++) {
        float4 a = wyp[q];
        float4 b = vp[q];
        vv[q*4+0] = 0.25f * a.x * b.x;
        vv[q*4+1] = 0.25f * a.y * b.y;
        vv[q*4+2] = 0.25f * a.z * b.z;
        vv[q*4+3] = 0.25f * a.w * b.w;
    }
    VV0p[(size_t)e * 32 + m] = tf32r(vv[0]);
    VV0p[(size_t)e * 32 + 16 + m] = 0.f;
    float o[16];
    #pragma unroll
    for (int j = 0; j < 16; j++) o[j] = 0.f;
    #pragma unroll
    for (int i = 0; i < 16; i++) {
        float t = vv[i];
        #pragma unroll
        for (int j = 0; j < 16; j++) o[j] += t * Wsh[i * 16 + j];
    }
    #pragma unroll
    for (int q = 0; q < 4; q++)
        vp[q] = make_float4(o[q*4], o[q*4+1], o[q*4+2], o[q*4+3]);
}

// ---------------- final readout ----------------
__global__ __launch_bounds__(256)
void k_final(const float* __restrict__ x, const float* __restrict__ u,
             const int* __restrict__ rcv, const float* __restrict__ Wout,
             float* __restrict__ out)
{
    __shared__ float Wo[256];
    int tid = threadIdx.x;
    Wo[tid] = Wout[tid];
    __syncthreads();
    int warp = tid >> 5, lane = tid & 31;
    size_t e = (size_t)blockIdx.x * 8 + warp;
    float p = 0.f;
    #pragma unroll
    for (int k = lane; k < 256; k += 32)
        p += x[e * 256 + k] * Wo[k];
    #pragma unroll
    for (int off = 16; off; off >>= 1)
        p += __shfl_xor_sync(0xffffffffu, p, off);
    if (lane == 0)
        atomicAdd(&out[rcv[e]], p * u[e] * 0.25f);
}

// ---------------- host ----------------
extern "C" void kernel_launch(void* const* d_in, const int* in_sizes, int n_in,
                              void* d_out, int out_size)
{
    const float* attrs = (const float*)d_in[0];
    const float* vec   = (const float*)d_in[1];
    const int*   snd   = (const int*)d_in[2];
    const int*   rcv   = (const int*)d_in[3];
    const float* We0   = (const float*)d_in[4];
    const float* be0   = (const float*)d_in[5];
    const float* We1   = (const float*)d_in[6];
    const float* be1   = (const float*)d_in[7];
    const float* Wv0   = (const float*)d_in[8];
    const float* Wlw   = (const float*)d_in[9];
    const float* Wlsh  = (const float*)d_in[10];
    const float* Wly1  = (const float*)d_in[11];
    const float* bly1  = (const float*)d_in[12];
    const float* Wly2  = (const float*)d_in[13];
    const float* bly2  = (const float*)d_in[14];
    const float* Wout  = (const float*)d_in[15];
    float* out = (float*)d_out;

    float *featp, *uu, *Y, *x, *t, *s16, *V, *VV0p, *wY, *Bt;
    cudaGetSymbolAddress((void**)&featp, g_featp);
    cudaGetSymbolAddress((void**)&uu,    g_u);
    cudaGetSymbolAddress((void**)&Y,     g_Y);
    cudaGetSymbolAddress((void**)&x,     g_x);
    cudaGetSymbolAddress((void**)&t,     g_t);
    cudaGetSymbolAddress((void**)&s16,   g_s16);
    cudaGetSymbolAddress((void**)&V,     g_V);
    cudaGetSymbolAddress((void**)&VV0p,  g_VV0p);
    cudaGetSymbolAddress((void**)&wY,    g_wY);
    cudaGetSymbolAddress((void**)&Bt,    g_Bt);

    // transposed weight regions [256][Kp]
    float* Bt_e0  = Bt + 0;        // Kp=64
    float* Bt_e1  = Bt + 16384;    // Kp=256
    float* Bt_l10 = Bt + 81920;    // Kp=288
    float* Bt_l11 = Bt + 155648;   // Kp=288
    float* Bt_l20 = Bt + 229376;   // Kp=256
    float* Bt_l21 = Bt + 294912;   // Kp=256

    const int SMEM_BYTES = SM_FLOATS * 4;   // 165888
    cudaFuncSetAttribute(mgemm<1>, cudaFuncAttributeMaxDynamicSharedMemorySize, SMEM_BYTES);
    cudaFuncSetAttribute(mgemm<2>, cudaFuncAttributeMaxDynamicSharedMemorySize, SMEM_BYTES);
    cudaFuncSetAttribute(mgemm<3>, cudaFuncAttributeMaxDynamicSharedMemorySize, SMEM_BYTES);

    // weight prep (transpose + pad + tf32 round)
    k_wprep<<<64, 256>>>(We0, Bt_e0, 40, 64);
    k_wprep<<<256, 256>>>(We1, Bt_e1, 256, 256);
    k_wprep<<<288, 256>>>(Wly1, Bt_l10, 272, 288);
    k_wprep<<<288, 256>>>(Wly1 + 272 * 256, Bt_l11, 272, 288);
    k_wprep<<<256, 256>>>(Wly2, Bt_l20, 256, 256);
    k_wprep<<<256, 256>>>(Wly2 + 256 * 256, Bt_l21, 256, 256);

    k_geom<<<EE / 256, 256>>>(vec, attrs, snd, rcv, featp, uu, Y);

    const int GB = EE / 128;   // 1024 CTAs
    mgemm<1><<<GB, 256, SMEM_BYTES>>>(featp, 64, 2, nullptr, Bt_e0, 64, 2, be0, nullptr, t);
    mgemm<2><<<GB, 256, SMEM_BYTES>>>(t, 256, 8, nullptr, Bt_e1, 256, 8, be1, uu, x);

    gemm_n16<<<EE / 128, 128>>>(x, Wv0, s16);
    k_buildV<<<EE * 16 / 256, 256>>>(s16, Y, V);

    for (int l = 0; l < 2; l++) {
        gemm_n16<<<EE / 128, 128>>>(x, Wlw + (size_t)l * 256 * 16, s16);
        k_zero4<<<(NN * 256 / 4 + 255) / 256, 256>>>((float4*)wY, NN * 256 / 4);
        k_scatter<<<EE * 16 / 256, 256>>>(s16, Y, snd, wY);
        k_update<<<EE * 16 / 256, 256>>>(snd, wY, V, VV0p, Wlsh + (size_t)l * 256);
        mgemm<1><<<GB, 256, SMEM_BYTES>>>(x, 256, 8, VV0p,
                                          (l == 0) ? Bt_l10 : Bt_l11, 288, 9,
                                          bly1 + (size_t)l * 256, nullptr, t);
        mgemm<3><<<GB, 256, SMEM_BYTES>>>(t, 256, 8, nullptr,
                                          (l == 0) ? Bt_l20 : Bt_l21, 256, 8,
                                          bly2 + (size_t)l * 256, uu, x);
    }

    k_zero4<<<(NN / 4 + 255) / 256, 256>>>((float4*)out, NN / 4);
    k_final<<<EE / 8, 256>>>(x, uu, rcv, Wout, out);
}